// round 15
// baseline (speedup 1.0000x reference)
#include <cuda_runtime.h>
#include <cuda_fp16.h>
#include <cstdint>

// Problem dims
#define NB 8
#define NS 4096
#define NF 256
#define NI 512
#define NI3 1536
#define ND 4
#define NKT 7
#define NV 256

#define RSTRIDE 40   // half-elements per smem row (80B) -> conflict-free ldmatrix
#define BM 128
#define BN 128
#define STAGES 4
#define A_STAGE_B (BM * RSTRIDE * 2)                 // 10240 B
#define B_STAGE_B (BN * RSTRIDE * 2)                 // 10240 B
#define SMEM_DYN (STAGES * (A_STAGE_B + B_STAGE_B))  // 81920 B; 2 CTAs/SM

// conv kernel smem plan: 4 A slots + 2 wide-B slots
#define C_ASLOT (BM * 80)                // 10240 B
#define C_BROWS 144                      // s in [n0-8, n0+135]
#define C_BSLOT (C_BROWS * 80)           // 11520 B
#define C_SMEM (4 * C_ASLOT + 2 * C_BSLOT)   // 64000 B; 2 CTAs/SM
#define NSTEP (NKT * (NI / 32))          // 112 steps (tap inner, ic outer)

// ---------------- device scratch ----------------
__device__ float g_P[(size_t)NB * NF * NS];            // [b][c][s] fp32 residual
__device__ float g_Q[(size_t)NB * NF * NS];            // [b][c][s] fp32 residual
__device__ __half g_y[(size_t)NB * NI3 * NS];          // [b][c][s] fp16 (mish outputs)
__device__ __half g_cat[(size_t)NB * NS * 2 * NF];     // [b][s][P|Q] fp16
__device__ __half g_vth[(size_t)NB * NS * NI + 8 * NI];// [b][s][512] fp16 (+8 pad rows)
__device__ __half g_w1h[(size_t)ND * NKT * NI3 * NI];  // [d][tap][o][i] fp16
__device__ __half g_w0h[(size_t)ND * NI3 * NF];
__device__ __half g_w2h[(size_t)ND * NF * NI];
__device__ __half g_owh[(size_t)NV * 2 * NF];

// ---------------- helpers ----------------
__device__ __forceinline__ uint32_t cvta_s(const void* p) {
    return (uint32_t)__cvta_generic_to_shared(p);
}
__device__ __forceinline__ void cpa16(uint32_t dst, const void* src, int sz) {
    asm volatile("cp.async.cg.shared.global [%0], [%1], 16, %2;"
                 :: "r"(dst), "l"(src), "r"(sz));
}
__device__ __forceinline__ void cp_commit() { asm volatile("cp.async.commit_group;"); }
__device__ __forceinline__ void cp_wait2() { asm volatile("cp.async.wait_group 2;"); }
__device__ __forceinline__ void cp_wait1() { asm volatile("cp.async.wait_group 1;"); }
__device__ __forceinline__ void cp_wait0() { asm volatile("cp.async.wait_group 0;"); }

__device__ __forceinline__ void ldm_x4(uint32_t r[4], uint32_t addr) {
    asm volatile("ldmatrix.sync.aligned.m8n8.x4.shared.b16 {%0,%1,%2,%3}, [%4];"
                 : "=r"(r[0]), "=r"(r[1]), "=r"(r[2]), "=r"(r[3]) : "r"(addr));
}
__device__ __forceinline__ void mma_f16(float c[4], const uint32_t a[4],
                                        uint32_t b0, uint32_t b1) {
    asm volatile(
        "mma.sync.aligned.m16n8k16.row.col.f32.f16.f16.f32 "
        "{%0,%1,%2,%3}, {%4,%5,%6,%7}, {%8,%9}, {%0,%1,%2,%3};"
        : "+f"(c[0]), "+f"(c[1]), "+f"(c[2]), "+f"(c[3])
        : "r"(a[0]), "r"(a[1]), "r"(a[2]), "r"(a[3]), "r"(b0), "r"(b1));
}
__device__ __forceinline__ float mishf(float x) {
    if (x > 20.0f) return x;
    float t = __expf(x);
    float u = t * t + 2.0f * t;
    return x * (u / (u + 2.0f));
}

// ---------------- prep kernels ----------------
// w1 [d][o][i][k] -> [d][k][o][i] fp16, coalesced both sides via smem stage.
// grid (NI3, ND), 256 threads; block handles one (d, o) slab of 512*7 floats.
__global__ void prep_w1_kernel(const float* __restrict__ w1) {
    __shared__ __half st[NKT][NI];
    int o = blockIdx.x, d = blockIdx.y, tid = threadIdx.x;
    const float* src = w1 + ((size_t)d * NI3 + o) * NI * NKT;
#pragma unroll
    for (int u = tid; u < NI * NKT; u += 256) {
        int i = u / NKT, t = u % NKT;
        st[t][i] = __float2half(src[u]);
    }
    __syncthreads();
#pragma unroll
    for (int u = tid; u < NKT * NI; u += 256) {
        int t = u / NI, i = u % NI;
        g_w1h[(((size_t)d * NKT + t) * NI3 + o) * NI + i] = st[t][i];
    }
}

#define NBLK_W0 ((int)(((size_t)ND * NI3 * NF) / 256))
#define NBLK_W2 ((int)(((size_t)ND * NF * NI) / 256))
#define NBLK_OW ((int)(((size_t)NV * 2 * NF) / 256))
__global__ void prep_wsmall_kernel(const float* __restrict__ w0,
                                   const float* __restrict__ w2,
                                   const float* __restrict__ ow) {
    int blk = blockIdx.x;
    int tid = threadIdx.x;
    if (blk < NBLK_W0) {
        size_t i = (size_t)blk * 256 + tid;
        g_w0h[i] = __float2half(w0[i]);
        return;
    }
    blk -= NBLK_W0;
    if (blk < NBLK_W2) {
        size_t i = (size_t)blk * 256 + tid;
        g_w2h[i] = __float2half(w2[i]);
        return;
    }
    blk -= NBLK_W2;
    size_t i = (size_t)blk * 256 + tid;
    g_owh[i] = __float2half(ow[i]);
}

__global__ void prep_emb_kernel(const int* __restrict__ inp, const float* __restrict__ emb) {
    int bx = blockIdx.x & 63, b = blockIdx.x >> 6;
    int tid = threadIdx.x;
    {
        int sx = tid & 63, cg = tid >> 6;
        int s = bx * 64 + sx;
        int idx = inp[b * NS + s];
        const float* er = emb + (size_t)idx * (2 * NF);
#pragma unroll 4
        for (int c = cg; c < NF; c += 4) {
            g_P[((size_t)b * NF + c) * NS + s] = er[c];
            g_Q[((size_t)b * NF + c) * NS + s] = er[c + NF];
        }
    }
    {
        int sx = tid >> 2, part = tid & 3;
        int s = bx * 64 + sx;
        int idx = inp[b * NS + s];
        const float* src = emb + (size_t)idx * (2 * NF) + part * 128;
        __half* dst = g_cat + ((size_t)b * NS + s) * (2 * NF) + part * 128;
#pragma unroll
        for (int u = 0; u < 128; u += 2) {
            *(half2*)(dst + u) = __floats2half2_rn(src[u], src[u + 1]);
        }
    }
}

// ---------------- fused lin_attn + transpose ----------------
__global__ void __launch_bounds__(256) linattn_t_kernel() {
    __shared__ __half stg[8][1032];

    int w = threadIdx.x >> 5, l = threadIdx.x & 31, tid = threadIdx.x;
    int i0 = blockIdx.x * 8, b = blockIdx.y;
    int i = i0 + w;

    const __half* dr = g_y + ((size_t)b * NI3 + i) * NS;
    const __half* sc = g_y + ((size_t)b * NI3 + NI + i) * NS;
    const __half* sh = g_y + ((size_t)b * NI3 + 2 * NI + i) * NS;

    float carry = 0.0f;
    for (int p = 0; p < 4; p++) {
        int sb = p * 1024 + l * 32;

        half2 dv[16];
#pragma unroll
        for (int q = 0; q < 4; q++)
            *(uint4*)(&dv[q * 4]) = *(const uint4*)(dr + sb + q * 8);
        float loc[32];
#pragma unroll
        for (int q = 0; q < 16; q++) {
            float2 f = __half22float2(dv[q]);
            loc[2 * q] = f.x;
            loc[2 * q + 1] = f.y;
        }
#pragma unroll
        for (int j = 1; j < 32; j++) loc[j] += loc[j - 1];
        float tot = loc[31];

        float incl = tot;
#pragma unroll
        for (int o = 1; o < 32; o <<= 1) {
            float n = __shfl_up_sync(0xffffffffu, incl, o);
            if (l >= o) incl += n;
        }
        float base = carry + incl - tot;
        carry += __shfl_sync(0xffffffffu, incl, 31);

        half2 scv[16], shv[16];
#pragma unroll
        for (int q = 0; q < 4; q++) {
            *(uint4*)(&scv[q * 4]) = *(const uint4*)(sc + sb + q * 8);
            *(uint4*)(&shv[q * 4]) = *(const uint4*)(sh + sb + q * 8);
        }
        half2 ov[16];
#pragma unroll
        for (int q = 0; q < 16; q++) {
            float2 s2 = __half22float2(scv[q]);
            float2 h2 = __half22float2(shv[q]);
            float r0 = (base + loc[2 * q]) / (float)(sb + 2 * q + 1) * s2.x + h2.x;
            float r1 = (base + loc[2 * q + 1]) / (float)(sb + 2 * q + 2) * s2.y + h2.y;
            ov[q] = __floats2half2_rn(r0, r1);
        }
#pragma unroll
        for (int q = 0; q < 4; q++)
            *(uint4*)(&stg[w][l * 32 + q * 8]) = *(uint4*)(&ov[q * 4]);

        __syncthreads();
#pragma unroll
        for (int rr = 0; rr < 4; rr++) {
            int r = tid + rr * 256;
            __half tmp[8];
#pragma unroll
            for (int c = 0; c < 8; c++) tmp[c] = stg[c][r];
            *(uint4*)(g_vth + ((size_t)b * NS + p * 1024 + r) * NI + i0) = *(uint4*)tmp;
        }
        __syncthreads();
    }
}

// ---------------- generic fp16 warp-MMA GEMM: 128x128, 4-stage k32, 3-ahead ----------------
// cmode: 0 -> g_y = mish(acc) fp16; 1 -> g_P += acc (+g_cat P-half); 2 -> g_Q += acc (+g_cat Q-half);
//        3 -> Cext = acc + bias.
__global__ void __launch_bounds__(256, 2) hgemm(
    const __half* __restrict__ A, int lda,
    const __half* __restrict__ B, int bstride, int KT,   // KT in k32 tiles
    int cmode, float* __restrict__ Cext, const float* __restrict__ bias)
{
    extern __shared__ __align__(16) char dsm[];
    uint32_t sbase = cvta_s(dsm);

    int t = threadIdx.x, lane = t & 31, warp = t >> 5;
    int n0 = blockIdx.x * BN, m0 = blockIdx.y * BM, b = blockIdx.z;
    int wm = (warp >> 2) * 64, wn = (warp & 3) * 32;

    float acc[4][4][4];
#pragma unroll
    for (int mi = 0; mi < 4; mi++)
#pragma unroll
        for (int ni = 0; ni < 4; ni++)
#pragma unroll
            for (int q = 0; q < 4; q++) acc[mi][ni][q] = 0.0f;

    int lrow = t >> 1;
    int lch = (t & 1) * 2;

    auto issue = [&](int kt) {
        int st = kt % STAGES;
        uint32_t ad = sbase + st * (A_STAGE_B + B_STAGE_B) + lrow * 80 + lch * 16;
        uint32_t bd = ad + A_STAGE_B;
        const __half* asrc = A + (size_t)(m0 + lrow) * lda + kt * 32 + lch * 8;
        const __half* bsrc = B + ((size_t)b * NS + n0 + lrow) * bstride + kt * 32 + lch * 8;
        cpa16(ad, asrc, 16);
        cpa16(ad + 16, asrc + 8, 16);
        cpa16(bd, bsrc, 16);
        cpa16(bd + 16, bsrc + 8, 16);
        cp_commit();
    };

    int a_row = (lane & 7) + 8 * ((lane >> 3) & 1);
    int a_kb = lane >> 4;
    int b_coff = (lane & 7) + 8 * (lane >> 4);
    int b_kb = (lane >> 3) & 1;

    issue(0);
    if (KT > 1) issue(1);
    if (KT > 2) issue(2);
    for (int kt = 0; kt < KT; kt++) {
        // wait so group kt is complete: pending allowed = min(2, KT-1-kt)
        int rem = KT - 1 - kt;
        if (rem >= 2) cp_wait2(); else if (rem == 1) cp_wait1(); else cp_wait0();
        __syncthreads();
        if (kt + 3 < KT) issue(kt + 3);
        uint32_t aT = sbase + (kt % STAGES) * (A_STAGE_B + B_STAGE_B);
        uint32_t bT = aT + A_STAGE_B;
#pragma unroll
        for (int sub = 0; sub < 2; sub++) {
            uint32_t af[4][4];
#pragma unroll
            for (int mi = 0; mi < 4; mi++) {
                uint32_t addr = aT + (wm + mi * 16 + a_row) * 80 + sub * 32 + a_kb * 16;
                ldm_x4(af[mi], addr);
            }
            uint32_t bf[2][4];
#pragma unroll
            for (int g = 0; g < 2; g++) {
                uint32_t addr = bT + (wn + g * 16 + b_coff) * 80 + sub * 32 + b_kb * 16;
                ldm_x4(bf[g], addr);
            }
#pragma unroll
            for (int mi = 0; mi < 4; mi++)
#pragma unroll
                for (int ni = 0; ni < 4; ni++)
                    mma_f16(acc[mi][ni], af[mi], bf[ni >> 1][(ni & 1) * 2],
                            bf[ni >> 1][(ni & 1) * 2 + 1]);
        }
    }

#pragma unroll
    for (int mi = 0; mi < 4; mi++) {
        int mlo = m0 + wm + mi * 16 + (lane >> 2);
#pragma unroll
        for (int ni = 0; ni < 4; ni++) {
            int n = n0 + wn + ni * 8 + 2 * (lane & 3);
            float* cc = acc[mi][ni];
#pragma unroll
            for (int hh = 0; hh < 2; hh++) {
                int m = mlo + hh * 8;
                float v0 = cc[hh * 2 + 0], v1 = cc[hh * 2 + 1];
                if (cmode == 0) {
                    half2 o = __floats2half2_rn(mishf(v0), mishf(v1));
                    *(half2*)(g_y + ((size_t)b * NI3 + m) * NS + n) = o;
                } else if (cmode == 1 || cmode == 2) {
                    float* X = (cmode == 1) ? g_P : g_Q;
                    int coff = (cmode == 1) ? 0 : NF;
                    float2* p = (float2*)(X + ((size_t)b * NF + m) * NS + n);
                    float2 e = *p;
                    e.x += v0; e.y += v1;
                    *p = e;
                    g_cat[((size_t)b * NS + n) * (2 * NF) + coff + m] = __float2half(e.x);
                    g_cat[((size_t)b * NS + n + 1) * (2 * NF) + coff + m] = __float2half(e.y);
                } else {
                    float bb = bias[m];
                    float2 o = make_float2(v0 + bb, v1 + bb);
                    *(float2*)(Cext + ((size_t)b * NV + m) * NS + n) = o;
                }
            }
        }
    }
}

// ---------------- conv GEMM: 7-tap B reuse, 4 A slots, 3-ahead, spread B prefetch ----------------
// j = ic*7 + tap. B(ic+1) fills spread across taps 3..6 (first write executes at loop
// iter ic*7, after the barrier closing B(ic-1)'s last read at iter ic*7-1 -> safe).
__global__ void __launch_bounds__(256, 2) hgemm_conv(
    const __half* __restrict__ A,   // g_w1h slice for depth d: [tap][o][i]
    const __half* __restrict__ B)   // g_vth: [b][s][i] (+8 pad rows at end)
{
    extern __shared__ __align__(16) char dsm[];
    uint32_t sbase = cvta_s(dsm);

    int t = threadIdx.x, lane = t & 31, warp = t >> 5;
    int n0 = blockIdx.x * BN, m0 = blockIdx.y * BM, b = blockIdx.z;
    int wm = (warp >> 2) * 64, wn = (warp & 3) * 32;

    float acc[4][4][4];
#pragma unroll
    for (int mi = 0; mi < 4; mi++)
#pragma unroll
        for (int ni = 0; ni < 4; ni++)
#pragma unroll
            for (int q = 0; q < 4; q++) acc[mi][ni][q] = 0.0f;

    int lrow = t >> 1;
    int lch = (t & 1) * 2;

    auto fill_b_chunk = [&](int ic_dst, int chunk) {
        int row = chunk >> 2, c4 = chunk & 3;
        int s = n0 - 8 + row;
        uint32_t bbase = sbase + 4 * C_ASLOT + (ic_dst & 1) * C_BSLOT;
        const __half* bsrc = B + ((size_t)b * NS + (s < 0 ? 0 : s)) * NI
                               + ic_dst * 32 + c4 * 8;
        cpa16(bbase + row * 80 + c4 * 16, bsrc, (s < 0) ? 0 : 16);
    };

    auto issue = [&](int j) {
        int tap = j % NKT, ic = j / NKT;
        uint32_t ad = sbase + (j & 3) * C_ASLOT + lrow * 80 + lch * 16;
        const __half* asrc = A + ((size_t)tap * NI3 + m0 + lrow) * NI + ic * 32 + lch * 8;
        cpa16(ad, asrc, 16);
        cpa16(ad + 16, asrc + 8, 16);
        if (j == 0) {
            if (t < 192) {
#pragma unroll
                for (int u = 0; u < 3; u++) fill_b_chunk(0, t * 3 + u);
            }
        } else if (tap >= 3 && ic + 1 < NI / 32 && t < 144) {
            int chunk = (tap - 3) * 144 + t;    // taps 3..6 x 144 = 576 chunks
            fill_b_chunk(ic + 1, chunk);
        }
        cp_commit();
    };

    int a_row = (lane & 7) + 8 * ((lane >> 3) & 1);
    int a_kb = lane >> 4;
    int b_coff = (lane & 7) + 8 * (lane >> 4);
    int b_kb = (lane >> 3) & 1;

    issue(0);
    issue(1);
    issue(2);
    for (int j = 0; j < NSTEP; j++) {
        int rem = NSTEP - 1 - j;
        if (rem >= 2) cp_wait2(); else if (rem == 1) cp_wait1(); else cp_wait0();
        __syncthreads();
        if (j + 3 < NSTEP) issue(j + 3);
        int tap = j % NKT, ic = j / NKT;
        uint32_t aT = sbase + (j & 3) * C_ASLOT;
        uint32_t bT = sbase + 4 * C_ASLOT + (ic & 1) * C_BSLOT;
        int brow0 = tap + 2;                     // tap shift = smem row offset
#pragma unroll
        for (int sub = 0; sub < 2; sub++) {
            uint32_t af[4][4];
#pragma unroll
            for (int mi = 0; mi < 4; mi++) {
                uint32_t addr = aT + (wm + mi * 16 + a_row) * 80 + sub * 32 + a_kb * 16;
                ldm_x4(af[mi], addr);
            }
            uint32_t bf[2][4];
#pragma unroll
            for (int g = 0; g < 2; g++) {
                uint32_t addr = bT + (wn + g * 16 + b_coff + brow0) * 80
                                   + sub * 32 + b_kb * 16;
                ldm_x4(bf[g], addr);
            }
#pragma unroll
            for (int mi = 0; mi < 4; mi++)
#pragma unroll
                for (int ni = 0; ni < 4; ni++)
                    mma_f16(acc[mi][ni], af[mi], bf[ni >> 1][(ni & 1) * 2],
                            bf[ni >> 1][(ni & 1) * 2 + 1]);
        }
    }

    // epilogue: g_y = mish(acc) fp16
#pragma unroll
    for (int mi = 0; mi < 4; mi++) {
        int mlo = m0 + wm + mi * 16 + (lane >> 2);
#pragma unroll
        for (int ni = 0; ni < 4; ni++) {
            int n = n0 + wn + ni * 8 + 2 * (lane & 3);
            float* cc = acc[mi][ni];
#pragma unroll
            for (int hh = 0; hh < 2; hh++) {
                int m = mlo + hh * 8;
                half2 o = __floats2half2_rn(mishf(cc[hh * 2 + 0]), mishf(cc[hh * 2 + 1]));
                *(half2*)(g_y + ((size_t)b * NI3 + m) * NS + n) = o;
            }
        }
    }
}

// ---------------- launch ----------------
extern "C" void kernel_launch(void* const* d_in, const int* in_sizes, int n_in,
                              void* d_out, int out_size) {
    (void)in_sizes; (void)n_in; (void)out_size;
    const int* inp = (const int*)d_in[0];
    const float* emb = (const float*)d_in[1];
    const float* w0 = (const float*)d_in[2];
    const float* w1 = (const float*)d_in[3];
    const float* w2 = (const float*)d_in[4];
    const float* out_w = (const float*)d_in[5];
    const float* out_b = (const float*)d_in[6];
    float* out = (float*)d_out;

    __half* gCAT; cudaGetSymbolAddress((void**)&gCAT, g_cat);
    __half* gVTH; cudaGetSymbolAddress((void**)&gVTH, g_vth);
    __half* gW1H; cudaGetSymbolAddress((void**)&gW1H, g_w1h);
    __half* gW0H; cudaGetSymbolAddress((void**)&gW0H, g_w0h);
    __half* gW2H; cudaGetSymbolAddress((void**)&gW2H, g_w2h);
    __half* gOWH; cudaGetSymbolAddress((void**)&gOWH, g_owh);

    cudaFuncSetAttribute(hgemm, cudaFuncAttributeMaxDynamicSharedMemorySize, SMEM_DYN);
    cudaFuncSetAttribute(hgemm_conv, cudaFuncAttributeMaxDynamicSharedMemorySize, C_SMEM);

    prep_w1_kernel<<<dim3(NI3, ND), 256>>>(w1);
    prep_wsmall_kernel<<<NBLK_W0 + NBLK_W2 + NBLK_OW, 256>>>(w0, w2, out_w);
    prep_emb_kernel<<<64 * NB, 256>>>(inp, emb);

    for (int d = 0; d < ND; d++) {
        const __half* xin = gCAT + ((d % 2 == 0) ? NF : 0);
        int accm = (d % 2 == 0) ? 1 : 2;

        hgemm<<<dim3(NS / BN, NI3 / BM, NB), 256, SMEM_DYN>>>(
            gW0H + (size_t)d * NI3 * NF, NF, xin, 2 * NF, NF / 32, 0, nullptr, nullptr);
        linattn_t_kernel<<<dim3(NI / 8, NB), 256>>>();

        hgemm_conv<<<dim3(NS / BN, NI3 / BM, NB), 256, C_SMEM>>>(
            gW1H + (size_t)d * NKT * NI3 * NI, gVTH);
        linattn_t_kernel<<<dim3(NI / 8, NB), 256>>>();

        hgemm<<<dim3(NS / BN, NF / BM, NB), 256, SMEM_DYN>>>(
            gW2H + (size_t)d * NF * NI, NI, gVTH, NI, NI / 32, accm, nullptr, nullptr);
    }

    hgemm<<<dim3(NS / BN, NV / BM, NB), 256, SMEM_DYN>>>(
        gOWH, 2 * NF, gCAT, 2 * NF, 2 * NF / 32, 3, out, out_b);
}

// round 16
// speedup vs baseline: 1.1150x; 1.1150x over previous
#include <cuda_runtime.h>
#include <cuda_fp16.h>
#include <cstdint>

// Problem dims
#define NB 8
#define NS 4096
#define NF 256
#define NI 512
#define NI3 1536
#define ND 4
#define NKT 7
#define NV 256

#define RSTRIDE 40   // half-elements per smem row (80B) -> conflict-free ldmatrix
#define BM 128
#define BN 128
#define STAGES 3
#define A_STAGE_B (BM * RSTRIDE * 2)                 // 10240 B
#define B_STAGE_B (BN * RSTRIDE * 2)                 // 10240 B
#define SMEM_DYN (STAGES * (A_STAGE_B + B_STAGE_B))  // 61440 B; 2 CTAs/SM

// conv kernel smem plan: 3 A slots + 2 wide-B slots
#define C_ASLOT (BM * 80)                // 10240 B
#define C_BROWS 144                      // s in [n0-8, n0+135]
#define C_BSLOT (C_BROWS * 80)           // 11520 B
#define C_SMEM (3 * C_ASLOT + 2 * C_BSLOT)   // 53760 B; 2 CTAs/SM
#define NSTEP (NKT * (NI / 32))          // 112 steps (tap inner, ic outer)

// ---------------- device scratch ----------------
__device__ float g_P[(size_t)NB * NF * NS];            // [b][c][s] fp32 residual
__device__ float g_Q[(size_t)NB * NF * NS];            // [b][c][s] fp32 residual
__device__ __half g_y[(size_t)NB * NI3 * NS];          // [b][c][s] fp16 (mish outputs)
__device__ __half g_cat[(size_t)NB * NS * 2 * NF];     // [b][s][P|Q] fp16
__device__ __half g_vth[(size_t)NB * NS * NI + 8 * NI];// [b][s][512] fp16 (+8 pad rows)
__device__ __half g_w1h[(size_t)ND * NKT * NI3 * NI];  // [d][tap][o][i] fp16
__device__ __half g_w0h[(size_t)ND * NI3 * NF];
__device__ __half g_w2h[(size_t)ND * NF * NI];
__device__ __half g_owh[(size_t)NV * 2 * NF];

// ---------------- helpers ----------------
__device__ __forceinline__ uint32_t cvta_s(const void* p) {
    return (uint32_t)__cvta_generic_to_shared(p);
}
__device__ __forceinline__ void cpa16(uint32_t dst, const void* src, int sz) {
    asm volatile("cp.async.cg.shared.global [%0], [%1], 16, %2;"
                 :: "r"(dst), "l"(src), "r"(sz));
}
__device__ __forceinline__ void cp_commit() { asm volatile("cp.async.commit_group;"); }
__device__ __forceinline__ void cp_wait1() { asm volatile("cp.async.wait_group 1;"); }
__device__ __forceinline__ void cp_wait0() { asm volatile("cp.async.wait_group 0;"); }

__device__ __forceinline__ void ldm_x4(uint32_t r[4], uint32_t addr) {
    asm volatile("ldmatrix.sync.aligned.m8n8.x4.shared.b16 {%0,%1,%2,%3}, [%4];"
                 : "=r"(r[0]), "=r"(r[1]), "=r"(r[2]), "=r"(r[3]) : "r"(addr));
}
__device__ __forceinline__ void mma_f16(float c[4], const uint32_t a[4],
                                        uint32_t b0, uint32_t b1) {
    asm volatile(
        "mma.sync.aligned.m16n8k16.row.col.f32.f16.f16.f32 "
        "{%0,%1,%2,%3}, {%4,%5,%6,%7}, {%8,%9}, {%0,%1,%2,%3};"
        : "+f"(c[0]), "+f"(c[1]), "+f"(c[2]), "+f"(c[3])
        : "r"(a[0]), "r"(a[1]), "r"(a[2]), "r"(a[3]), "r"(b0), "r"(b1));
}
__device__ __forceinline__ float mishf(float x) {
    if (x > 20.0f) return x;
    float t = __expf(x);
    float u = t * t + 2.0f * t;
    return x * (u / (u + 2.0f));
}

// ---------------- prep kernels ----------------
// w1 [d][o][i][k] -> [d][k][o][i] fp16, coalesced both sides via smem stage.
// grid (NI3, ND), 256 threads; block handles one (d, o) slab of 512*7 floats.
__global__ void prep_w1_kernel(const float* __restrict__ w1) {
    __shared__ __half st[NKT][NI];
    int o = blockIdx.x, d = blockIdx.y, tid = threadIdx.x;
    const float* src = w1 + ((size_t)d * NI3 + o) * NI * NKT;
    for (int u = tid; u < NI * NKT; u += 256) {
        int i = u / NKT, t = u % NKT;
        st[t][i] = __float2half(src[u]);
    }
    __syncthreads();
    for (int u = tid; u < NKT * NI; u += 256) {
        int t = u / NI, i = u % NI;
        g_w1h[(((size_t)d * NKT + t) * NI3 + o) * NI + i] = st[t][i];
    }
}

#define NBLK_W0 ((int)(((size_t)ND * NI3 * NF) / 256))
#define NBLK_W2 ((int)(((size_t)ND * NF * NI) / 256))
#define NBLK_OW ((int)(((size_t)NV * 2 * NF) / 256))
__global__ void prep_wsmall_kernel(const float* __restrict__ w0,
                                   const float* __restrict__ w2,
                                   const float* __restrict__ ow) {
    int blk = blockIdx.x;
    int tid = threadIdx.x;
    if (blk < NBLK_W0) {
        size_t i = (size_t)blk * 256 + tid;
        g_w0h[i] = __float2half(w0[i]);
        return;
    }
    blk -= NBLK_W0;
    if (blk < NBLK_W2) {
        size_t i = (size_t)blk * 256 + tid;
        g_w2h[i] = __float2half(w2[i]);
        return;
    }
    blk -= NBLK_W2;
    size_t i = (size_t)blk * 256 + tid;
    g_owh[i] = __float2half(ow[i]);
}

__global__ void prep_emb_kernel(const int* __restrict__ inp, const float* __restrict__ emb) {
    int bx = blockIdx.x & 63, b = blockIdx.x >> 6;
    int tid = threadIdx.x;
    {
        int sx = tid & 63, cg = tid >> 6;
        int s = bx * 64 + sx;
        int idx = inp[b * NS + s];
        const float* er = emb + (size_t)idx * (2 * NF);
#pragma unroll 4
        for (int c = cg; c < NF; c += 4) {
            g_P[((size_t)b * NF + c) * NS + s] = er[c];
            g_Q[((size_t)b * NF + c) * NS + s] = er[c + NF];
        }
    }
    {
        int sx = tid >> 2, part = tid & 3;
        int s = bx * 64 + sx;
        int idx = inp[b * NS + s];
        const float* src = emb + (size_t)idx * (2 * NF) + part * 128;
        __half* dst = g_cat + ((size_t)b * NS + s) * (2 * NF) + part * 128;
#pragma unroll
        for (int u = 0; u < 128; u += 2) {
            *(half2*)(dst + u) = __floats2half2_rn(src[u], src[u + 1]);
        }
    }
}

// ---------------- fused lin_attn + transpose ----------------
__global__ void __launch_bounds__(256) linattn_t_kernel() {
    __shared__ __half stg[8][1032];

    int w = threadIdx.x >> 5, l = threadIdx.x & 31, tid = threadIdx.x;
    int i0 = blockIdx.x * 8, b = blockIdx.y;
    int i = i0 + w;

    const __half* dr = g_y + ((size_t)b * NI3 + i) * NS;
    const __half* sc = g_y + ((size_t)b * NI3 + NI + i) * NS;
    const __half* sh = g_y + ((size_t)b * NI3 + 2 * NI + i) * NS;

    float carry = 0.0f;
    for (int p = 0; p < 4; p++) {
        int sb = p * 1024 + l * 32;

        half2 dv[16];
#pragma unroll
        for (int q = 0; q < 4; q++)
            *(uint4*)(&dv[q * 4]) = *(const uint4*)(dr + sb + q * 8);
        float loc[32];
#pragma unroll
        for (int q = 0; q < 16; q++) {
            float2 f = __half22float2(dv[q]);
            loc[2 * q] = f.x;
            loc[2 * q + 1] = f.y;
        }
#pragma unroll
        for (int j = 1; j < 32; j++) loc[j] += loc[j - 1];
        float tot = loc[31];

        float incl = tot;
#pragma unroll
        for (int o = 1; o < 32; o <<= 1) {
            float n = __shfl_up_sync(0xffffffffu, incl, o);
            if (l >= o) incl += n;
        }
        float base = carry + incl - tot;
        carry += __shfl_sync(0xffffffffu, incl, 31);

        half2 scv[16], shv[16];
#pragma unroll
        for (int q = 0; q < 4; q++) {
            *(uint4*)(&scv[q * 4]) = *(const uint4*)(sc + sb + q * 8);
            *(uint4*)(&shv[q * 4]) = *(const uint4*)(sh + sb + q * 8);
        }
        half2 ov[16];
#pragma unroll
        for (int q = 0; q < 16; q++) {
            float2 s2 = __half22float2(scv[q]);
            float2 h2 = __half22float2(shv[q]);
            float r0 = (base + loc[2 * q]) / (float)(sb + 2 * q + 1) * s2.x + h2.x;
            float r1 = (base + loc[2 * q + 1]) / (float)(sb + 2 * q + 2) * s2.y + h2.y;
            ov[q] = __floats2half2_rn(r0, r1);
        }
#pragma unroll
        for (int q = 0; q < 4; q++)
            *(uint4*)(&stg[w][l * 32 + q * 8]) = *(uint4*)(&ov[q * 4]);

        __syncthreads();
#pragma unroll
        for (int rr = 0; rr < 4; rr++) {
            int r = tid + rr * 256;
            __half tmp[8];
#pragma unroll
            for (int c = 0; c < 8; c++) tmp[c] = stg[c][r];
            *(uint4*)(g_vth + ((size_t)b * NS + p * 1024 + r) * NI + i0) = *(uint4*)tmp;
        }
        __syncthreads();
    }
}

// ---------------- generic fp16 warp-MMA GEMM (w0 / w2 / final): 128x128, 3-stage k32 ----------------
// cmode: 0 -> g_y = mish(acc) fp16; 1 -> g_P += acc (+g_cat P-half); 2 -> g_Q += acc (+g_cat Q-half);
//        3 -> Cext = acc + bias.
__global__ void __launch_bounds__(256, 2) hgemm(
    const __half* __restrict__ A, int lda,
    const __half* __restrict__ B, int bstride, int KT,   // KT in k32 tiles
    int cmode, float* __restrict__ Cext, const float* __restrict__ bias)
{
    extern __shared__ __align__(16) char dsm[];
    uint32_t sbase = cvta_s(dsm);

    int t = threadIdx.x, lane = t & 31, warp = t >> 5;
    int n0 = blockIdx.x * BN, m0 = blockIdx.y * BM, b = blockIdx.z;
    int wm = (warp >> 2) * 64, wn = (warp & 3) * 32;

    float acc[4][4][4];
#pragma unroll
    for (int mi = 0; mi < 4; mi++)
#pragma unroll
        for (int ni = 0; ni < 4; ni++)
#pragma unroll
            for (int q = 0; q < 4; q++) acc[mi][ni][q] = 0.0f;

    int lrow = t >> 1;
    int lch = (t & 1) * 2;

    auto issue = [&](int kt) {
        int st = kt % STAGES;
        uint32_t ad = sbase + st * (A_STAGE_B + B_STAGE_B) + lrow * 80 + lch * 16;
        uint32_t bd = ad + A_STAGE_B;
        const __half* asrc = A + (size_t)(m0 + lrow) * lda + kt * 32 + lch * 8;
        const __half* bsrc = B + ((size_t)b * NS + n0 + lrow) * bstride + kt * 32 + lch * 8;
        cpa16(ad, asrc, 16);
        cpa16(ad + 16, asrc + 8, 16);
        cpa16(bd, bsrc, 16);
        cpa16(bd + 16, bsrc + 8, 16);
        cp_commit();
    };

    int a_row = (lane & 7) + 8 * ((lane >> 3) & 1);
    int a_kb = lane >> 4;
    int b_coff = (lane & 7) + 8 * (lane >> 4);
    int b_kb = (lane >> 3) & 1;

    issue(0);
    if (KT > 1) issue(1);
    for (int kt = 0; kt < KT; kt++) {
        if (kt + 1 < KT) cp_wait1(); else cp_wait0();
        __syncthreads();
        if (kt + 2 < KT) issue(kt + 2);
        uint32_t aT = sbase + (kt % STAGES) * (A_STAGE_B + B_STAGE_B);
        uint32_t bT = aT + A_STAGE_B;
#pragma unroll
        for (int sub = 0; sub < 2; sub++) {
            uint32_t af[4][4];
#pragma unroll
            for (int mi = 0; mi < 4; mi++) {
                uint32_t addr = aT + (wm + mi * 16 + a_row) * 80 + sub * 32 + a_kb * 16;
                ldm_x4(af[mi], addr);
            }
            uint32_t bf[2][4];
#pragma unroll
            for (int g = 0; g < 2; g++) {
                uint32_t addr = bT + (wn + g * 16 + b_coff) * 80 + sub * 32 + b_kb * 16;
                ldm_x4(bf[g], addr);
            }
#pragma unroll
            for (int mi = 0; mi < 4; mi++)
#pragma unroll
                for (int ni = 0; ni < 4; ni++)
                    mma_f16(acc[mi][ni], af[mi], bf[ni >> 1][(ni & 1) * 2],
                            bf[ni >> 1][(ni & 1) * 2 + 1]);
        }
    }

#pragma unroll
    for (int mi = 0; mi < 4; mi++) {
        int mlo = m0 + wm + mi * 16 + (lane >> 2);
#pragma unroll
        for (int ni = 0; ni < 4; ni++) {
            int n = n0 + wn + ni * 8 + 2 * (lane & 3);
            float* cc = acc[mi][ni];
#pragma unroll
            for (int hh = 0; hh < 2; hh++) {
                int m = mlo + hh * 8;
                float v0 = cc[hh * 2 + 0], v1 = cc[hh * 2 + 1];
                if (cmode == 0) {
                    half2 o = __floats2half2_rn(mishf(v0), mishf(v1));
                    *(half2*)(g_y + ((size_t)b * NI3 + m) * NS + n) = o;
                } else if (cmode == 1 || cmode == 2) {
                    float* X = (cmode == 1) ? g_P : g_Q;
                    int coff = (cmode == 1) ? 0 : NF;
                    float2* p = (float2*)(X + ((size_t)b * NF + m) * NS + n);
                    float2 e = *p;
                    e.x += v0; e.y += v1;
                    *p = e;
                    g_cat[((size_t)b * NS + n) * (2 * NF) + coff + m] = __float2half(e.x);
                    g_cat[((size_t)b * NS + n + 1) * (2 * NF) + coff + m] = __float2half(e.y);
                } else {
                    float bb = bias[m];
                    float2 o = make_float2(v0 + bb, v1 + bb);
                    *(float2*)(Cext + ((size_t)b * NV + m) * NS + n) = o;
                }
            }
        }
    }
}

// ---------------- conv GEMM with 7-tap B reuse + spread B prefetch (R14-proven) ----------------
// j = ic*7 + tap. A tiles stream in a 3-slot ring; B(ic+1) wide tile (144 rows x 32i)
// fills spread across taps 2..6 of ic (slot-hazard-safe); B(0) bursts in group 0.
__global__ void __launch_bounds__(256, 2) hgemm_conv(
    const __half* __restrict__ A,   // g_w1h slice for depth d: [tap][o][i]
    const __half* __restrict__ B)   // g_vth: [b][s][i] (+8 pad rows at end)
{
    extern __shared__ __align__(16) char dsm[];
    uint32_t sbase = cvta_s(dsm);

    int t = threadIdx.x, lane = t & 31, warp = t >> 5;
    int n0 = blockIdx.x * BN, m0 = blockIdx.y * BM, b = blockIdx.z;
    int wm = (warp >> 2) * 64, wn = (warp & 3) * 32;

    float acc[4][4][4];
#pragma unroll
    for (int mi = 0; mi < 4; mi++)
#pragma unroll
        for (int ni = 0; ni < 4; ni++)
#pragma unroll
            for (int q = 0; q < 4; q++) acc[mi][ni][q] = 0.0f;

    int lrow = t >> 1;
    int lch = (t & 1) * 2;

    auto fill_b_chunk = [&](int ic_dst, int chunk) {
        int row = chunk >> 2, c4 = chunk & 3;
        int s = n0 - 8 + row;
        uint32_t bbase = sbase + 3 * C_ASLOT + (ic_dst & 1) * C_BSLOT;
        const __half* bsrc = B + ((size_t)b * NS + (s < 0 ? 0 : s)) * NI
                               + ic_dst * 32 + c4 * 8;
        cpa16(bbase + row * 80 + c4 * 16, bsrc, (s < 0) ? 0 : 16);
    };

    auto issue = [&](int j) {
        int tap = j % NKT, ic = j / NKT;
        uint32_t ad = sbase + (j % 3) * C_ASLOT + lrow * 80 + lch * 16;
        const __half* asrc = A + ((size_t)tap * NI3 + m0 + lrow) * NI + ic * 32 + lch * 8;
        cpa16(ad, asrc, 16);
        cpa16(ad + 16, asrc + 8, 16);
        if (j == 0) {
            if (t < 192) {
#pragma unroll
                for (int u = 0; u < 3; u++) fill_b_chunk(0, t * 3 + u);
            }
        } else if (tap >= 2 && ic + 1 < NI / 32 && t < 116) {
            int chunk = (tap - 2) * 116 + t;
            if (chunk < 576) fill_b_chunk(ic + 1, chunk);
        }
        cp_commit();
    };

    int a_row = (lane & 7) + 8 * ((lane >> 3) & 1);
    int a_kb = lane >> 4;
    int b_coff = (lane & 7) + 8 * (lane >> 4);
    int b_kb = (lane >> 3) & 1;

    issue(0);
    issue(1);
    for (int j = 0; j < NSTEP; j++) {
        if (j + 1 < NSTEP) cp_wait1(); else cp_wait0();
        __syncthreads();
        if (j + 2 < NSTEP) issue(j + 2);
        int tap = j % NKT, ic = j / NKT;
        uint32_t aT = sbase + (j % 3) * C_ASLOT;
        uint32_t bT = sbase + 3 * C_ASLOT + (ic & 1) * C_BSLOT;
        int brow0 = tap + 2;
#pragma unroll
        for (int sub = 0; sub < 2; sub++) {
            uint32_t af[4][4];
#pragma unroll
            for (int mi = 0; mi < 4; mi++) {
                uint32_t addr = aT + (wm + mi * 16 + a_row) * 80 + sub * 32 + a_kb * 16;
                ldm_x4(af[mi], addr);
            }
            uint32_t bf[2][4];
#pragma unroll
            for (int g = 0; g < 2; g++) {
                uint32_t addr = bT + (wn + g * 16 + b_coff + brow0) * 80
                                   + sub * 32 + b_kb * 16;
                ldm_x4(bf[g], addr);
            }
#pragma unroll
            for (int mi = 0; mi < 4; mi++)
#pragma unroll
                for (int ni = 0; ni < 4; ni++)
                    mma_f16(acc[mi][ni], af[mi], bf[ni >> 1][(ni & 1) * 2],
                            bf[ni >> 1][(ni & 1) * 2 + 1]);
        }
    }

    // epilogue: g_y = mish(acc) fp16
#pragma unroll
    for (int mi = 0; mi < 4; mi++) {
        int mlo = m0 + wm + mi * 16 + (lane >> 2);
#pragma unroll
        for (int ni = 0; ni < 4; ni++) {
            int n = n0 + wn + ni * 8 + 2 * (lane & 3);
            float* cc = acc[mi][ni];
#pragma unroll
            for (int hh = 0; hh < 2; hh++) {
                int m = mlo + hh * 8;
                half2 o = __floats2half2_rn(mishf(cc[hh * 2 + 0]), mishf(cc[hh * 2 + 1]));
                *(half2*)(g_y + ((size_t)b * NI3 + m) * NS + n) = o;
            }
        }
    }
}

// ---------------- launch ----------------
extern "C" void kernel_launch(void* const* d_in, const int* in_sizes, int n_in,
                              void* d_out, int out_size) {
    (void)in_sizes; (void)n_in; (void)out_size;
    const int* inp = (const int*)d_in[0];
    const float* emb = (const float*)d_in[1];
    const float* w0 = (const float*)d_in[2];
    const float* w1 = (const float*)d_in[3];
    const float* w2 = (const float*)d_in[4];
    const float* out_w = (const float*)d_in[5];
    const float* out_b = (const float*)d_in[6];
    float* out = (float*)d_out;

    __half* gCAT; cudaGetSymbolAddress((void**)&gCAT, g_cat);
    __half* gVTH; cudaGetSymbolAddress((void**)&gVTH, g_vth);
    __half* gW1H; cudaGetSymbolAddress((void**)&gW1H, g_w1h);
    __half* gW0H; cudaGetSymbolAddress((void**)&gW0H, g_w0h);
    __half* gW2H; cudaGetSymbolAddress((void**)&gW2H, g_w2h);
    __half* gOWH; cudaGetSymbolAddress((void**)&gOWH, g_owh);

    cudaFuncSetAttribute(hgemm, cudaFuncAttributeMaxDynamicSharedMemorySize, SMEM_DYN);
    cudaFuncSetAttribute(hgemm_conv, cudaFuncAttributeMaxDynamicSharedMemorySize, C_SMEM);

    prep_w1_kernel<<<dim3(NI3, ND), 256>>>(w1);
    prep_wsmall_kernel<<<NBLK_W0 + NBLK_W2 + NBLK_OW, 256>>>(w0, w2, out_w);
    prep_emb_kernel<<<64 * NB, 256>>>(inp, emb);

    for (int d = 0; d < ND; d++) {
        const __half* xin = gCAT + ((d % 2 == 0) ? NF : 0);
        int accm = (d % 2 == 0) ? 1 : 2;

        hgemm<<<dim3(NS / BN, NI3 / BM, NB), 256, SMEM_DYN>>>(
            gW0H + (size_t)d * NI3 * NF, NF, xin, 2 * NF, NF / 32, 0, nullptr, nullptr);
        linattn_t_kernel<<<dim3(NI / 8, NB), 256>>>();

        hgemm_conv<<<dim3(NS / BN, NI3 / BM, NB), 256, C_SMEM>>>(
            gW1H + (size_t)d * NKT * NI3 * NI, gVTH);
        linattn_t_kernel<<<dim3(NI / 8, NB), 256>>>();

        hgemm<<<dim3(NS / BN, NF / BM, NB), 256, SMEM_DYN>>>(
            gW2H + (size_t)d * NF * NI, NI, gVTH, NI, NI / 32, accm, nullptr, nullptr);
    }

    hgemm<<<dim3(NS / BN, NV / BM, NB), 256, SMEM_DYN>>>(
        gOWH, 2 * NF, gCAT, 2 * NF, 2 * NF / 32, 3, out, out_b);
}